// round 14
// baseline (speedup 1.0000x reference)
#include <cuda_runtime.h>
#include <math.h>

#define TT 128
#define BB 32
#define EE 512
#define HH 512
#define UU 1024
#define VV 10000
#define G4 2048   // 4*H

#define NBLK 128
#define SMEM_LSTM (131072 + 32768 + 32768)   // Wt + hsd + Pp[2] = 192KB
#define SMEM_GEMM 61440                      // 2 stages x 30720B

// ---------------- scratch (static device globals; no allocation) ----------------
__device__ __align__(128) float g_X1 [TT*G4*BB];   // pregates [t][g4][b]
__device__ __align__(128) float g_X2 [TT*G4*BB];
__device__ __align__(128) float g_S  [TT*BB*UU];   // fp32 scores
// tf32 hi/lo operand buffers
__device__ __align__(128) float g_INh[TT*BB*EE],  g_INl[TT*BB*EE];
__device__ __align__(128) float g_W1h[G4*EE],     g_W1l[G4*EE];
__device__ __align__(128) float g_W2h[G4*HH],     g_W2l[G4*HH];
__device__ __align__(128) float g_WOh[VV*HH],     g_WOl[VV*HH];
__device__ __align__(128) float g_Lh [UU*BB*HH],  g_Ll [UU*BB*HH];
__device__ __align__(128) float g_H1h[TT*BB*HH],  g_H1l[TT*BB*HH];
__device__ __align__(128) float g_Sh [TT*BB*UU],  g_Sl [TT*BB*UU];
__device__ __align__(128) float g_CXh[TT*BB*HH],  g_CXl[TT*BB*HH];
__device__ __align__(128) float g_HSh[TT*BB*HH],  g_HSl[TT*BB*HH];
__device__ __align__(128) float g_HT [2][4*512*8]; // parity h [bg][k][b8]
__device__ unsigned g_flag[NBLK];

// ---------------- helpers ----------------
typedef unsigned long long ull;
__device__ __forceinline__ ull pack2(float x) {
    ull r;
    asm("mov.b64 %0, {%1, %1};" : "=l"(r) : "r"(__float_as_uint(x)));
    return r;
}
__device__ __forceinline__ void fma2(ull& d, ull a, ull b) {
    asm("fma.rn.f32x2 %0, %1, %2, %0;" : "+l"(d) : "l"(a), "l"(b));
}
__device__ __forceinline__ unsigned ld_acq(const unsigned* p) {
    unsigned v;
    asm volatile("ld.acquire.gpu.global.u32 %0, [%1];" : "=r"(v) : "l"(p));
    return v;
}
__device__ __forceinline__ void st_rel(unsigned* p, unsigned v) {
    asm volatile("st.release.gpu.global.u32 [%0], %1;" :: "l"(p), "r"(v) : "memory");
}
__device__ __forceinline__ float fsig(float x) {
    return __fdividef(1.f, 1.f + __expf(-x));
}
__device__ __forceinline__ float ftanh_(float x) {
    float a = fabsf(x);
    float t = 1.f - __fdividef(2.f, __expf(2.f * a) + 1.f);
    return copysignf(t, x);
}
__device__ __forceinline__ float tf32r(float f) {
    unsigned u;
    asm("cvt.rna.tf32.f32 %0, %1;" : "=r"(u) : "f"(f));
    return __uint_as_float(u);
}
__device__ __forceinline__ unsigned smem_u32(const void* p) {
    unsigned a;
    asm("{ .reg .u64 t; cvta.to.shared.u64 t, %1; cvt.u32.u64 %0, t; }"
        : "=r"(a) : "l"(p));
    return a;
}
__device__ __forceinline__ void cpa16(unsigned dst, const void* src, unsigned sz) {
    asm volatile("cp.async.cg.shared.global [%0], [%1], 16, %2;"
                 :: "r"(dst), "l"(src), "r"(sz));
}

// ---------------- tf32 hi/lo split (elementwise, float4) ----------------
__global__ void split_tf32(const float4* __restrict__ src,
                           float4* __restrict__ hi, float4* __restrict__ lo)
{
    int i = blockIdx.x * 256 + threadIdx.x;
    float4 v = src[i], h, l;
    h.x = tf32r(v.x); l.x = tf32r(v.x - h.x);
    h.y = tf32r(v.y); l.y = tf32r(v.y - h.y);
    h.z = tf32r(v.z); l.z = tf32r(v.z - h.z);
    h.w = tf32r(v.w); l.w = tf32r(v.w - h.w);
    hi[i] = h; lo[i] = l;
}

// ---------------- prep: reset flags, h0 -> g_HT[1] ----------------
__global__ void prep(const float* __restrict__ h0row)
{
    int tid = threadIdx.x;
    if (tid < NBLK) g_flag[tid] = 0;
    for (int idx = tid; idx < BB * HH; idx += 256) {
        int b = idx >> 9, h = idx & 511;
        g_HT[1][(b >> 3) * 4096 + h * 8 + (b & 7)] = h0row[idx];
    }
}

// ---------------- persistent LSTM recurrence v2 ---------------------------------
// Block (hc, bg). Warp w = k-slice [64w,64w+64): deps ONLY on blocks 4w..4w+3 of
// its own bg. Per step per warp: poll own 4 flags -> stage private hsd slice
// (warp-private, syncwarp only) -> compute -> store partials (parity).
// ONE block barrier; reducers (tid<128) reduce, pointwise (fast-math), publish,
// release; warps 4-7 run ahead into step t+1.
__global__ __launch_bounds__(256)
void lstm_seq(const float* __restrict__ XT,     // [T][G4][B] pregates
              const float* __restrict__ Whh,    // [G4][H]
              const float* __restrict__ c0row,  // [B][H]
              float* __restrict__ Hh,           // [T][B][H] tf32-hi
              float* __restrict__ Hl)           // [T][B][H] tf32-lo
{
    extern __shared__ char smraw[];
    float* Wt  = (float*)smraw;                   // [512][64]
    ull*   hsd = (ull*)(smraw + 131072);          // [512][8] (warp-private slices)
    ull*   Pp  = (ull*)(smraw + 131072 + 32768);  // [2][8][32][8] parity partials

    const int bid = blockIdx.x;
    const int tid = threadIdx.x;
    const int hc  = bid & 31;
    const int bg  = bid >> 5;

    for (int idx = tid; idx < 64 * 128; idx += 256) {
        int r  = idx & 63;
        int k4 = idx >> 6;
        int g = r >> 4, j = r & 15;
        int gr = g * 512 + 16 * hc + j;
        float4 w = *(const float4*)(Whh + (size_t)gr * HH + k4 * 4);
        Wt[(k4 * 4 + 0) * 64 + r] = w.x;
        Wt[(k4 * 4 + 1) * 64 + r] = w.y;
        Wt[(k4 * 4 + 2) * 64 + r] = w.z;
        Wt[(k4 * 4 + 3) * 64 + r] = w.w;
    }

    const int warp = tid >> 5;
    const int lane = tid & 31;
    const int rg   = lane >> 1;
    const int bq   = lane & 1;
    const int kbeg = warp * 64;

    const int j  = tid >> 3;
    const int bb = tid & 7;
    float cv = 0.f;
    if (tid < 128) cv = c0row[(8 * bg + bb) * HH + 16 * hc + j];

    unsigned* myflag = &g_flag[bid];
    const unsigned* dep = &g_flag[bg * 32 + warp * 4];   // 4 deps per warp

    __syncthreads();   // Wt staged

    for (int t = 0; t < TT; t++) {
        const int p = t & 1;

        // ---- per-warp wait on own 4 producers ----
        if (t > 0) {
            if (lane < 4) {
                const unsigned* f = dep + lane;
                while (ld_acq(f) < (unsigned)t) { }
            }
        }
        __syncwarp();

        // ---- stage own 64-k h slice (warp-private) ----
        {
            const float4* src = (const float4*)&g_HT[(t + 1) & 1][bg * 4096];
            #pragma unroll
            for (int r = 0; r < 4; r++) {
                int i = kbeg * 2 + lane + r * 32;     // float4 index
                float4 v = __ldcg(src + i);
                int k  = i >> 1;
                int b0 = (i & 1) * 4;
                ull* d = &hsd[k * 8 + b0];
                d[0] = pack2(v.x); d[1] = pack2(v.y);
                d[2] = pack2(v.z); d[3] = pack2(v.w);
            }
        }

        // ---- XT gate prefetch (reducer threads; LDGs fly under compute) ----
        float xg0 = 0.f, xg1 = 0.f, xg2 = 0.f, xg3 = 0.f;
        if (tid < 128) {
            const float* xb = XT + ((size_t)t * G4 + 16 * hc + j) * BB
                              + 8 * bg + bb;
            xg0 = __ldcg(xb);
            xg1 = __ldcg(xb + (size_t)512  * BB);
            xg2 = __ldcg(xb + (size_t)1024 * BB);
            xg3 = __ldcg(xb + (size_t)1536 * BB);
        }
        __syncwarp();

        // ---- compute ----
        ull acc[2][4];
        #pragma unroll
        for (int i = 0; i < 2; i++)
            #pragma unroll
            for (int q = 0; q < 4; q++) acc[i][q] = 0ull;

        #pragma unroll 4
        for (int k = kbeg; k < kbeg + 64; k++) {
            ulonglong2 wp = *(const ulonglong2*)&Wt[k * 64 + rg * 4];
            ulonglong2 hA = *(const ulonglong2*)&hsd[k * 8 + bq * 4];
            ulonglong2 hB = *(const ulonglong2*)&hsd[k * 8 + bq * 4 + 2];
            fma2(acc[0][0], wp.x, hA.x); fma2(acc[0][1], wp.x, hA.y);
            fma2(acc[0][2], wp.x, hB.x); fma2(acc[0][3], wp.x, hB.y);
            fma2(acc[1][0], wp.y, hA.x); fma2(acc[1][1], wp.y, hA.y);
            fma2(acc[1][2], wp.y, hB.x); fma2(acc[1][3], wp.y, hB.y);
        }

        // ---- store partials (parity p) ----
        {
            ull* pb = &Pp[(size_t)p * 2048 + ((warp * 32) + rg * 2) * 8 + bq * 4];
            *(ulonglong2*)(pb + 0)  = make_ulonglong2(acc[0][0], acc[0][1]);
            *(ulonglong2*)(pb + 2)  = make_ulonglong2(acc[0][2], acc[0][3]);
            *(ulonglong2*)(pb + 8)  = make_ulonglong2(acc[1][0], acc[1][1]);
            *(ulonglong2*)(pb + 10) = make_ulonglong2(acc[1][2], acc[1][3]);
        }
        __syncthreads();   // ONLY block barrier per step

        // ---- reduce + pointwise + publish (warps 0-3); warps 4-7 run ahead ----
        if (tid < 128) {
            const float* pf = (const float*)(Pp + (size_t)p * 2048);
            float gv[4] = {xg0, xg1, xg2, xg3};
            #pragma unroll
            for (int g = 0; g < 4; g++) {
                int r  = g * 16 + j;
                int rp = r >> 1, ln = r & 1;
                float s = 0.f;
                #pragma unroll
                for (int sI = 0; sI < 8; sI++)
                    s += pf[((sI * 32 + rp) * 8 + bb) * 2 + ln];
                gv[g] += s;
            }
            float gi = fsig(gv[0]);
            float gf = fsig(gv[1]);
            float gg = ftanh_(gv[2]);
            float go = fsig(gv[3]);
            cv = gf * cv + gi * gg;
            float hv = go * ftanh_(cv);
            g_HT[p][bg * 4096 + (16 * hc + j) * 8 + bb] = hv;

            asm volatile("bar.sync 1, 128;" ::: "memory");
            if (tid == 0) st_rel(myflag, (unsigned)(t + 1));

            // archive tf32 hi/lo off the inter-block critical path
            size_t idx = (size_t)t * BB * HH + (8 * bg + bb) * HH + 16 * hc + j;
            float hh = tf32r(hv);
            Hh[idx] = hh;
            Hl[idx] = tf32r(hv - hh);
        }
    }
}

// ---------------- tf32x3 tensor GEMM v3 (R13, unchanged) ------------------------
#define TPB 20
#define TPN 72
__global__ __launch_bounds__(256)
void gemm_v3(const float* __restrict__ Ahg, const float* __restrict__ Alg,
             const float* __restrict__ Bhg, const float* __restrict__ Blg,
             float* __restrict__ C, float* __restrict__ Ch, float* __restrict__ Cl,
             const float* __restrict__ bias1, const float* __restrict__ bias2,
             int M, int N, int K, int lda, int ldb, int ldc,
             long long aBS, long long bBS, long long cBS,
             int transC, int bTrans)
{
    extern __shared__ float smf[];
    const unsigned sbase = smem_u32(smf);

    const int tid  = threadIdx.x;
    const int warp = tid >> 5;
    const int lane = tid & 31;
    const int wm = warp >> 1;
    const int wn = warp & 1;
    const int gq  = lane >> 2;
    const int tig = lane & 3;

    const int m0 = blockIdx.y * 128;
    const int n0 = blockIdx.x * 64;

    const float* Abh = Ahg + (long long)blockIdx.z * aBS;
    const float* Abl = Alg + (long long)blockIdx.z * aBS;
    const float* Bbh = Bhg + (long long)blockIdx.z * bBS;
    const float* Bbl = Blg + (long long)blockIdx.z * bBS;

    float c[2][4][4];
    #pragma unroll
    for (int ta = 0; ta < 2; ta++)
        #pragma unroll
        for (int tb = 0; tb < 4; tb++)
            #pragma unroll
            for (int q = 0; q < 4; q++) c[ta][tb][q] = 0.f;

    auto load_stage = [&](int s, int kt) {
        unsigned sb = sbase + s * 30720;
        #pragma unroll
        for (int r = 0; r < 2; r++) {
            int sgi = tid + r * 256;
            int row = sgi >> 2, ks = (sgi & 3) << 2;
            size_t off = (size_t)(m0 + row) * lda + kt + ks;
            unsigned d = sb + (unsigned)(row * TPB + ks) * 4;
            cpa16(d,         Abh + off, 16);
            cpa16(d + 10240, Abl + off, 16);
        }
        if (!bTrans) {
            int row = tid >> 2, ks = (tid & 3) << 2;
            int n = n0 + row;
            unsigned sz = (n < N) ? 16u : 0u;
            size_t off = (size_t)(n < N ? n : 0) * ldb + kt + ks;
            unsigned d = sb + 20480 + (unsigned)(row * TPB + ks) * 4;
            cpa16(d,        Bbh + off, sz);
            cpa16(d + 5120, Bbl + off, sz);
        } else {
            int k = tid >> 4, ns = (tid & 15) << 2;
            size_t off = (size_t)(kt + k) * ldb + n0 + ns;
            unsigned d = sb + 20480 + (unsigned)(k * TPN + ns) * 4;
            cpa16(d,        Bbh + off, 16);
            cpa16(d + 5120, Bbl + off, 16);
        }
        asm volatile("cp.async.commit_group;");
    };

    const int nt = K >> 4;
    load_stage(0, 0);
    int buf = 0;

    for (int it = 0; it < nt; it++) {
        if (it + 1 < nt) {
            load_stage(buf ^ 1, (it + 1) << 4);
            asm volatile("cp.async.wait_group 1;");
        } else {
            asm volatile("cp.async.wait_group 0;");
        }
        __syncthreads();

        const float* Ah = smf + buf * 7680;
        const float* Al = Ah + 2560;
        const float* Bh = Ah + 5120;
        const float* Bl = Ah + 6400;

        #pragma unroll
        for (int k8 = 0; k8 < 16; k8 += 8) {
            unsigned ah[2][4], al[2][4], bh[4][2], bl[4][2];
            #pragma unroll
            for (int ta = 0; ta < 2; ta++) {
                int base = (wm * 32 + ta * 16 + gq) * TPB + k8 + tig;
                ah[ta][0] = __float_as_uint(Ah[base]);
                ah[ta][1] = __float_as_uint(Ah[base + 8 * TPB]);
                ah[ta][2] = __float_as_uint(Ah[base + 4]);
                ah[ta][3] = __float_as_uint(Ah[base + 8 * TPB + 4]);
                al[ta][0] = __float_as_uint(Al[base]);
                al[ta][1] = __float_as_uint(Al[base + 8 * TPB]);
                al[ta][2] = __float_as_uint(Al[base + 4]);
                al[ta][3] = __float_as_uint(Al[base + 8 * TPB + 4]);
            }
            #pragma unroll
            for (int tb = 0; tb < 4; tb++) {
                if (!bTrans) {
                    int base = (wn * 32 + tb * 8 + gq) * TPB + k8 + tig;
                    bh[tb][0] = __float_as_uint(Bh[base]);
                    bh[tb][1] = __float_as_uint(Bh[base + 4]);
                    bl[tb][0] = __float_as_uint(Bl[base]);
                    bl[tb][1] = __float_as_uint(Bl[base + 4]);
                } else {
                    int base = (k8 + tig) * TPN + wn * 32 + tb * 8 + gq;
                    bh[tb][0] = __float_as_uint(Bh[base]);
                    bh[tb][1] = __float_as_uint(Bh[base + 4 * TPN]);
                    bl[tb][0] = __float_as_uint(Bl[base]);
                    bl[tb][1] = __float_as_uint(Bl[base + 4 * TPN]);
                }
            }
            #pragma unroll
            for (int ta = 0; ta < 2; ta++)
                #pragma unroll
                for (int tb = 0; tb < 4; tb++) {
                    float* cc = c[ta][tb];
                    asm volatile(
                        "mma.sync.aligned.m16n8k8.row.col.f32.tf32.tf32.f32 "
                        "{%0,%1,%2,%3}, {%4,%5,%6,%7}, {%8,%9}, {%0,%1,%2,%3};"
                        : "+f"(cc[0]), "+f"(cc[1]), "+f"(cc[2]), "+f"(cc[3])
                        : "r"(ah[ta][0]), "r"(ah[ta][1]), "r"(ah[ta][2]), "r"(ah[ta][3]),
                          "r"(bh[tb][0]), "r"(bh[tb][1]));
                    asm volatile(
                        "mma.sync.aligned.m16n8k8.row.col.f32.tf32.tf32.f32 "
                        "{%0,%1,%2,%3}, {%4,%5,%6,%7}, {%8,%9}, {%0,%1,%2,%3};"
                        : "+f"(cc[0]), "+f"(cc[1]), "+f"(cc[2]), "+f"(cc[3])
                        : "r"(ah[ta][0]), "r"(ah[ta][1]), "r"(ah[ta][2]), "r"(ah[ta][3]),
                          "r"(bl[tb][0]), "r"(bl[tb][1]));
                    asm volatile(
                        "mma.sync.aligned.m16n8k8.row.col.f32.tf32.tf32.f32 "
                        "{%0,%1,%2,%3}, {%4,%5,%6,%7}, {%8,%9}, {%0,%1,%2,%3};"
                        : "+f"(cc[0]), "+f"(cc[1]), "+f"(cc[2]), "+f"(cc[3])
                        : "r"(al[ta][0]), "r"(al[ta][1]), "r"(al[ta][2]), "r"(al[ta][3]),
                          "r"(bh[tb][0]), "r"(bh[tb][1]));
                }
        }
        __syncthreads();
        buf ^= 1;
    }

    float* Cb  = C  ? C  + (long long)blockIdx.z * cBS : (float*)0;
    float* Chb = Ch ? Ch + (long long)blockIdx.z * cBS : (float*)0;
    float* Clb = Cl ? Cl + (long long)blockIdx.z * cBS : (float*)0;

    #pragma unroll
    for (int ta = 0; ta < 2; ta++) {
        int mrow = m0 + wm * 32 + ta * 16 + gq;
        #pragma unroll
        for (int tb = 0; tb < 4; tb++) {
            int ncol = n0 + wn * 32 + tb * 8 + 2 * tig;
            #pragma unroll
            for (int half = 0; half < 2; half++) {
                int m = mrow + half * 8;
                #pragma unroll
                for (int q = 0; q < 2; q++) {
                    int n = ncol + q;
                    if (n < N) {
                        float v = c[ta][tb][half * 2 + q];
                        if (bias1) v += bias1[n];
                        if (bias2) v += bias2[n];
                        size_t idx = transC
                            ? ((size_t)(m >> 5) * G4 + n) * BB + (m & 31)
                            : (size_t)m * ldc + n;
                        if (Cb) Cb[idx] = v;
                        if (Chb) {
                            float hh = tf32r(v);
                            Chb[idx] = hh;
                            Clb[idx] = tf32r(v - hh);
                        }
                    }
                }
            }
        }
    }
}

// ---------------- softmax: in-place fp32 ----------------
__global__ __launch_bounds__(256)
void softmax_rows(float* __restrict__ data, int L)
{
    float* p = data + (size_t)blockIdx.x * L;
    __shared__ float red[256];
    const int tid = threadIdx.x;

    float m = -3.4e38f;
    for (int i = tid; i < L; i += 256) m = fmaxf(m, p[i]);
    red[tid] = m; __syncthreads();
    #pragma unroll
    for (int s = 128; s > 0; s >>= 1) {
        if (tid < s) red[tid] = fmaxf(red[tid], red[tid + s]);
        __syncthreads();
    }
    m = red[0]; __syncthreads();

    float sum = 0.f;
    for (int i = tid; i < L; i += 256) {
        float e = expf(p[i] - m);
        p[i] = e;
        sum += e;
    }
    red[tid] = sum; __syncthreads();
    #pragma unroll
    for (int s = 128; s > 0; s >>= 1) {
        if (tid < s) red[tid] += red[tid + s];
        __syncthreads();
    }
    const float inv = 1.f / red[0];
    for (int i = tid; i < L; i += 256) p[i] *= inv;
}

// ---------------- softmax + tf32 split output ----------------
__global__ __launch_bounds__(256)
void softmax_split(const float* __restrict__ in,
                   float* __restrict__ oh, float* __restrict__ ol, int L)
{
    const float* p = in + (size_t)blockIdx.x * L;
    float* ph = oh + (size_t)blockIdx.x * L;
    float* pl = ol + (size_t)blockIdx.x * L;
    __shared__ float red[256];
    const int tid = threadIdx.x;

    float m = -3.4e38f;
    for (int i = tid; i < L; i += 256) m = fmaxf(m, p[i]);
    red[tid] = m; __syncthreads();
    #pragma unroll
    for (int s = 128; s > 0; s >>= 1) {
        if (tid < s) red[tid] = fmaxf(red[tid], red[tid + s]);
        __syncthreads();
    }
    m = red[0]; __syncthreads();

    float sum = 0.f;
    for (int i = tid; i < L; i += 256) sum += expf(p[i] - m);
    red[tid] = sum; __syncthreads();
    #pragma unroll
    for (int s = 128; s > 0; s >>= 1) {
        if (tid < s) red[tid] += red[tid + s];
        __syncthreads();
    }
    const float inv = 1.f / red[0];
    for (int i = tid; i < L; i += 256) {
        float w = expf(p[i] - m) * inv;
        float hh = tf32r(w);
        ph[i] = hh;
        pl[i] = tf32r(w - hh);
    }
}

// ---------------- launch ----------------
extern "C" void kernel_launch(void* const* d_in, const int* in_sizes, int n_in,
                              void* d_out, int out_size)
{
    const float* inputs = (const float*)d_in[0];
    const float* h0     = (const float*)d_in[1];
    const float* c0     = (const float*)d_in[2];
    const float* Lst    = (const float*)d_in[3];
    const float* W_ih1  = (const float*)d_in[4];
    const float* W_hh1  = (const float*)d_in[5];
    const float* b_ih1  = (const float*)d_in[6];
    const float* b_hh1  = (const float*)d_in[7];
    const float* W_ih2  = (const float*)d_in[8];
    const float* W_hh2  = (const float*)d_in[9];
    const float* b_ih2  = (const float*)d_in[10];
    const float* b_hh2  = (const float*)d_in[11];
    const float* W_out  = (const float*)d_in[12];
    const float* b_out  = (const float*)d_in[13];
    float* out = (float*)d_out;

    void* p;
    cudaGetSymbolAddress(&p, g_X1);  float* X1  = (float*)p;
    cudaGetSymbolAddress(&p, g_X2);  float* X2  = (float*)p;
    cudaGetSymbolAddress(&p, g_S);   float* S   = (float*)p;
    cudaGetSymbolAddress(&p, g_INh); float* INh = (float*)p;
    cudaGetSymbolAddress(&p, g_INl); float* INl = (float*)p;
    cudaGetSymbolAddress(&p, g_W1h); float* W1h = (float*)p;
    cudaGetSymbolAddress(&p, g_W1l); float* W1l = (float*)p;
    cudaGetSymbolAddress(&p, g_W2h); float* W2h = (float*)p;
    cudaGetSymbolAddress(&p, g_W2l); float* W2l = (float*)p;
    cudaGetSymbolAddress(&p, g_WOh); float* WOh = (float*)p;
    cudaGetSymbolAddress(&p, g_WOl); float* WOl = (float*)p;
    cudaGetSymbolAddress(&p, g_Lh);  float* Lh  = (float*)p;
    cudaGetSymbolAddress(&p, g_Ll);  float* Ll  = (float*)p;
    cudaGetSymbolAddress(&p, g_H1h); float* H1h = (float*)p;
    cudaGetSymbolAddress(&p, g_H1l); float* H1l = (float*)p;
    cudaGetSymbolAddress(&p, g_Sh);  float* Sh  = (float*)p;
    cudaGetSymbolAddress(&p, g_Sl);  float* Sl  = (float*)p;
    cudaGetSymbolAddress(&p, g_CXh); float* CXh = (float*)p;
    cudaGetSymbolAddress(&p, g_CXl); float* CXl = (float*)p;
    cudaGetSymbolAddress(&p, g_HSh); float* HSh = (float*)p;
    cudaGetSymbolAddress(&p, g_HSl); float* HSl = (float*)p;

    cudaFuncSetAttribute(lstm_seq, cudaFuncAttributeMaxDynamicSharedMemorySize,
                         SMEM_LSTM);
    cudaFuncSetAttribute(gemm_v3, cudaFuncAttributeMaxDynamicSharedMemorySize,
                         SMEM_GEMM);

    // operand splits
    split_tf32<<<TT*BB*EE/1024, 256>>>((const float4*)inputs, (float4*)INh, (float4*)INl);
    split_tf32<<<G4*EE/1024,   256>>>((const float4*)W_ih1, (float4*)W1h, (float4*)W1l);
    split_tf32<<<G4*HH/1024,   256>>>((const float4*)W_ih2, (float4*)W2h, (float4*)W2l);
    split_tf32<<<VV*HH/1024,   256>>>((const float4*)W_out, (float4*)WOh, (float4*)WOl);
    split_tf32<<<UU*BB*HH/1024,256>>>((const float4*)Lst,   (float4*)Lh,  (float4*)Ll);

    // X1 = inputs @ W_ih1^T + biases -> [t][g4][b]
    {
        dim3 g(G4 / 64, (TT * BB) / 128, 1);
        gemm_v3<<<g, 256, SMEM_GEMM>>>(INh, INl, W1h, W1l, X1, 0, 0,
                                       b_ih1, b_hh1,
                                       TT * BB, G4, EE, EE, EE, G4,
                                       0, 0, 0, 1, 0);
    }

    // layer-1 recurrence -> H1 hi/lo
    prep<<<1, 256>>>(h0);
    lstm_seq<<<NBLK, 256, SMEM_LSTM>>>(X1, W_hh1, c0, H1h, H1l);

    // S = H1 @ L^T (batched)
    {
        dim3 g(UU / 64, 1, BB);
        gemm_v3<<<g, 256, SMEM_GEMM>>>(H1h, H1l, Lh, Ll, S, 0, 0,
                                       0, 0,
                                       TT, UU, HH, BB * HH, BB * HH, BB * UU,
                                       HH, HH, UU, 0, 0);
    }
    softmax_split<<<TT * BB, 256>>>(S, Sh, Sl, UU);

    // CTX = softmax(S) @ L (NN), epilogue writes tf32 hi/lo
    {
        dim3 g(HH / 64, 1, BB);
        gemm_v3<<<g, 256, SMEM_GEMM>>>(Sh, Sl, Lh, Ll, 0, CXh, CXl,
                                       0, 0,
                                       TT, HH, UU, BB * UU, BB * HH, BB * HH,
                                       UU, HH, HH, 0, 1);
    }

    // X2 = CTX @ W_ih2^T + biases -> [t][g4][b]
    {
        dim3 g(G4 / 64, (TT * BB) / 128, 1);
        gemm_v3<<<g, 256, SMEM_GEMM>>>(CXh, CXl, W2h, W2l, X2, 0, 0,
                                       b_ih2, b_hh2,
                                       TT * BB, G4, HH, HH, HH, G4,
                                       0, 0, 0, 1, 0);
    }

    // layer-2 recurrence -> HS hi/lo
    prep<<<1, 256>>>(h0 + BB * HH);
    lstm_seq<<<NBLK, 256, SMEM_LSTM>>>(X2, W_hh2, c0 + BB * HH, HSh, HSl);

    // logits = HS @ W_out^T + b_out -> softmax over V
    {
        dim3 g((VV + 63) / 64, (TT * BB) / 128, 1);
        gemm_v3<<<g, 256, SMEM_GEMM>>>(HSh, HSl, WOh, WOl, out, 0, 0,
                                       b_out, 0,
                                       TT * BB, VV, HH, HH, HH, VV,
                                       0, 0, 0, 0, 0);
    }
    softmax_rows<<<TT * BB, 256>>>(out, VV);
}

// round 15
// speedup vs baseline: 1.5875x; 1.5875x over previous
#include <cuda_runtime.h>
#include <math.h>

#define TT 128
#define BB 32
#define EE 512
#define HH 512
#define UU 1024
#define VV 10000
#define G4 2048   // 4*H

#define NBLK 128
#define SMEM_LSTM (131072 + 32768 + 32768)   // Wt + hsd + Pp[2] = 192KB
#define SMEM_GEMM 61440                      // 2 stages x 30720B

// ---------------- scratch (static device globals; no allocation) ----------------
__device__ __align__(128) float g_X1 [TT*G4*BB];   // pregates [t][g4][b]
__device__ __align__(128) float g_X2 [TT*G4*BB];
__device__ __align__(128) float g_S  [TT*BB*UU];   // fp32 scores
// tf32 hi/lo operand buffers
__device__ __align__(128) float g_INh[TT*BB*EE],  g_INl[TT*BB*EE];
__device__ __align__(128) float g_W1h[G4*EE],     g_W1l[G4*EE];
__device__ __align__(128) float g_W2h[G4*HH],     g_W2l[G4*HH];
__device__ __align__(128) float g_WOh[VV*HH],     g_WOl[VV*HH];
__device__ __align__(128) float g_Lh [UU*BB*HH],  g_Ll [UU*BB*HH];
__device__ __align__(128) float g_H1h[TT*BB*HH],  g_H1l[TT*BB*HH];
__device__ __align__(128) float g_Sh [TT*BB*UU],  g_Sl [TT*BB*UU];
__device__ __align__(128) float g_CXh[TT*BB*HH],  g_CXl[TT*BB*HH];
__device__ __align__(128) float g_HSh[TT*BB*HH],  g_HSl[TT*BB*HH];
__device__ __align__(128) float g_HT [2][4*512*8]; // parity h [bg][k][b8]
__device__ unsigned g_flag[NBLK];

// ---------------- helpers ----------------
typedef unsigned long long ull;
__device__ __forceinline__ ull pack2(float x) {
    ull r;
    asm("mov.b64 %0, {%1, %1};" : "=l"(r) : "r"(__float_as_uint(x)));
    return r;
}
__device__ __forceinline__ void fma2(ull& d, ull a, ull b) {
    asm("fma.rn.f32x2 %0, %1, %2, %0;" : "+l"(d) : "l"(a), "l"(b));
}
__device__ __forceinline__ unsigned ld_acq(const unsigned* p) {
    unsigned v;
    asm volatile("ld.acquire.gpu.global.u32 %0, [%1];" : "=r"(v) : "l"(p));
    return v;
}
__device__ __forceinline__ void st_rel(unsigned* p, unsigned v) {
    asm volatile("st.release.gpu.global.u32 [%0], %1;" :: "l"(p), "r"(v) : "memory");
}
__device__ __forceinline__ float sigmoidf_(float x) { return 1.f / (1.f + expf(-x)); }
__device__ __forceinline__ float tf32r(float f) {
    unsigned u;
    asm("cvt.rna.tf32.f32 %0, %1;" : "=r"(u) : "f"(f));
    return __uint_as_float(u);
}
__device__ __forceinline__ unsigned smem_u32(const void* p) {
    unsigned a;
    asm("{ .reg .u64 t; cvta.to.shared.u64 t, %1; cvt.u32.u64 %0, t; }"
        : "=r"(a) : "l"(p));
    return a;
}
__device__ __forceinline__ void cpa16(unsigned dst, const void* src, unsigned sz) {
    asm volatile("cp.async.cg.shared.global [%0], [%1], 16, %2;"
                 :: "r"(dst), "l"(src), "r"(sz));
}

// ---------------- tf32 hi/lo split (elementwise, float4) ----------------
__global__ void split_tf32(const float4* __restrict__ src,
                           float4* __restrict__ hi, float4* __restrict__ lo)
{
    int i = blockIdx.x * 256 + threadIdx.x;
    float4 v = src[i], h, l;
    h.x = tf32r(v.x); l.x = tf32r(v.x - h.x);
    h.y = tf32r(v.y); l.y = tf32r(v.y - h.y);
    h.z = tf32r(v.z); l.z = tf32r(v.z - h.z);
    h.w = tf32r(v.w); l.w = tf32r(v.w - h.w);
    hi[i] = h; lo[i] = l;
}

// ---------------- prep: reset flags, h0 -> g_HT[1] ----------------
__global__ void prep(const float* __restrict__ h0row)
{
    int tid = threadIdx.x;
    if (tid < NBLK) g_flag[tid] = 0;
    for (int idx = tid; idx < BB * HH; idx += 256) {
        int b = idx >> 9, h = idx & 511;
        g_HT[1][(b >> 3) * 4096 + h * 8 + (b & 7)] = h0row[idx];
    }
}

// ---------------- persistent LSTM recurrence (R13 + parity partials) ------------
// R13 structure exactly, except: Pp parity-buffered so the trailing barrier is
// deleted. Non-reducer warps proceed to step t+1's FIRST syncthreads and BLOCK
// (no spinning) until warp 0 finishes reduce + release. One fewer barrier/step.
__global__ __launch_bounds__(256)
void lstm_seq(const float* __restrict__ XT,     // [T][G4][B] pregates
              const float* __restrict__ Whh,    // [G4][H]
              const float* __restrict__ c0row,  // [B][H]
              float* __restrict__ Hh,           // [T][B][H] tf32-hi
              float* __restrict__ Hl)           // [T][B][H] tf32-lo
{
    extern __shared__ char smraw[];
    float* Wt  = (float*)smraw;                   // [512][64]
    ull*   hsd = (ull*)(smraw + 131072);          // [512][8]
    ull*   Pp  = (ull*)(smraw + 131072 + 32768);  // [2][8][32][8] parity partials

    const int bid = blockIdx.x;
    const int tid = threadIdx.x;
    const int hc  = bid & 31;
    const int bg  = bid >> 5;

    for (int idx = tid; idx < 64 * 128; idx += 256) {
        int r  = idx & 63;
        int k4 = idx >> 6;
        int g = r >> 4, j = r & 15;
        int gr = g * 512 + 16 * hc + j;
        float4 w = *(const float4*)(Whh + (size_t)gr * HH + k4 * 4);
        Wt[(k4 * 4 + 0) * 64 + r] = w.x;
        Wt[(k4 * 4 + 1) * 64 + r] = w.y;
        Wt[(k4 * 4 + 2) * 64 + r] = w.z;
        Wt[(k4 * 4 + 3) * 64 + r] = w.w;
    }

    const int warp = tid >> 5;
    const int lane = tid & 31;
    const int rg   = lane >> 1;
    const int bq   = lane & 1;
    const int kbeg = warp * 64;

    const int j  = tid >> 3;
    const int bb = tid & 7;
    float cv = 0.f;
    if (tid < 128) cv = c0row[(8 * bg + bb) * HH + 16 * hc + j];

    unsigned* myflag = &g_flag[bid];
    const unsigned* grpflags = &g_flag[bg * 32];

    for (int t = 0; t < TT; t++) {
        const int p = t & 1;

        if (t > 0) {
            if (tid < 32) {
                const unsigned* f = grpflags + tid;
                while (ld_acq(f) < (unsigned)t) { }
            }
        }
        __syncthreads();   // #1: flags acquired; also orders Wt (t=0), hsd WAR

        // ---- stage h_{t-1} ----
        {
            const float4* src = (const float4*)&g_HT[(t + 1) & 1][bg * 4096];
            #pragma unroll
            for (int r = 0; r < 4; r++) {
                int i = tid + r * 256;
                float4 v = __ldcg(src + i);
                int k  = i >> 1;
                int b0 = (i & 1) * 4;
                ull* d = &hsd[k * 8 + b0];
                d[0] = pack2(v.x); d[1] = pack2(v.y);
                d[2] = pack2(v.z); d[3] = pack2(v.w);
            }
        }

        // ---- XT gate prefetch (reducers) ----
        float xg0 = 0.f, xg1 = 0.f, xg2 = 0.f, xg3 = 0.f;
        if (tid < 128) {
            const float* xb = XT + ((size_t)t * G4 + 16 * hc + j) * BB
                              + 8 * bg + bb;
            xg0 = __ldcg(xb);
            xg1 = __ldcg(xb + (size_t)512  * BB);
            xg2 = __ldcg(xb + (size_t)1024 * BB);
            xg3 = __ldcg(xb + (size_t)1536 * BB);
        }
        __syncthreads();   // #2: hsd staged

        ull acc[2][4];
        #pragma unroll
        for (int i = 0; i < 2; i++)
            #pragma unroll
            for (int q = 0; q < 4; q++) acc[i][q] = 0ull;

        #pragma unroll 4
        for (int k = kbeg; k < kbeg + 64; k++) {
            ulonglong2 wp = *(const ulonglong2*)&Wt[k * 64 + rg * 4];
            ulonglong2 hA = *(const ulonglong2*)&hsd[k * 8 + bq * 4];
            ulonglong2 hB = *(const ulonglong2*)&hsd[k * 8 + bq * 4 + 2];
            fma2(acc[0][0], wp.x, hA.x); fma2(acc[0][1], wp.x, hA.y);
            fma2(acc[0][2], wp.x, hB.x); fma2(acc[0][3], wp.x, hB.y);
            fma2(acc[1][0], wp.y, hA.x); fma2(acc[1][1], wp.y, hA.y);
            fma2(acc[1][2], wp.y, hB.x); fma2(acc[1][3], wp.y, hB.y);
        }

        {
            ull* pb = &Pp[(size_t)p * 2048 + ((warp * 32) + rg * 2) * 8 + bq * 4];
            *(ulonglong2*)(pb + 0)  = make_ulonglong2(acc[0][0], acc[0][1]);
            *(ulonglong2*)(pb + 2)  = make_ulonglong2(acc[0][2], acc[0][3]);
            *(ulonglong2*)(pb + 8)  = make_ulonglong2(acc[1][0], acc[1][1]);
            *(ulonglong2*)(pb + 10) = make_ulonglong2(acc[1][2], acc[1][3]);
        }
        __syncthreads();   // #3: partials visible

        // ---- reduce + pointwise + publish (tid<128); warps 4-7 go to t+1 ----
        if (tid < 128) {
            const float* pf = (const float*)(Pp + (size_t)p * 2048);
            float gv[4] = {xg0, xg1, xg2, xg3};
            #pragma unroll
            for (int g = 0; g < 4; g++) {
                int r  = g * 16 + j;
                int rp = r >> 1, ln = r & 1;
                float s = 0.f;
                #pragma unroll
                for (int sI = 0; sI < 8; sI++)
                    s += pf[((sI * 32 + rp) * 8 + bb) * 2 + ln];
                gv[g] += s;
            }
            float gi = sigmoidf_(gv[0]);
            float gf = sigmoidf_(gv[1]);
            float gg = tanhf(gv[2]);
            float go = sigmoidf_(gv[3]);
            cv = gf * cv + gi * gg;
            float hv = go * tanhf(cv);
            g_HT[p][bg * 4096 + (16 * hc + j) * 8 + bb] = hv;

            asm volatile("bar.sync 1, 128;" ::: "memory");
            if (tid == 0) st_rel(myflag, (unsigned)(t + 1));

            size_t idx = (size_t)t * BB * HH + (8 * bg + bb) * HH + 16 * hc + j;
            float hh = tf32r(hv);
            Hh[idx] = hh;
            Hl[idx] = tf32r(hv - hh);
        }
        // no trailing __syncthreads: warps 4-7 block at #1 of step t+1
    }
}

// ---------------- tf32x3 tensor GEMM v3 (R13, unchanged) ------------------------
#define TPB 20
#define TPN 72
__global__ __launch_bounds__(256)
void gemm_v3(const float* __restrict__ Ahg, const float* __restrict__ Alg,
             const float* __restrict__ Bhg, const float* __restrict__ Blg,
             float* __restrict__ C, float* __restrict__ Ch, float* __restrict__ Cl,
             const float* __restrict__ bias1, const float* __restrict__ bias2,
             int M, int N, int K, int lda, int ldb, int ldc,
             long long aBS, long long bBS, long long cBS,
             int transC, int bTrans)
{
    extern __shared__ float smf[];
    const unsigned sbase = smem_u32(smf);

    const int tid  = threadIdx.x;
    const int warp = tid >> 5;
    const int lane = tid & 31;
    const int wm = warp >> 1;
    const int wn = warp & 1;
    const int gq  = lane >> 2;
    const int tig = lane & 3;

    const int m0 = blockIdx.y * 128;
    const int n0 = blockIdx.x * 64;

    const float* Abh = Ahg + (long long)blockIdx.z * aBS;
    const float* Abl = Alg + (long long)blockIdx.z * aBS;
    const float* Bbh = Bhg + (long long)blockIdx.z * bBS;
    const float* Bbl = Blg + (long long)blockIdx.z * bBS;

    float c[2][4][4];
    #pragma unroll
    for (int ta = 0; ta < 2; ta++)
        #pragma unroll
        for (int tb = 0; tb < 4; tb++)
            #pragma unroll
            for (int q = 0; q < 4; q++) c[ta][tb][q] = 0.f;

    auto load_stage = [&](int s, int kt) {
        unsigned sb = sbase + s * 30720;
        #pragma unroll
        for (int r = 0; r < 2; r++) {
            int sgi = tid + r * 256;
            int row = sgi >> 2, ks = (sgi & 3) << 2;
            size_t off = (size_t)(m0 + row) * lda + kt + ks;
            unsigned d = sb + (unsigned)(row * TPB + ks) * 4;
            cpa16(d,         Abh + off, 16);
            cpa16(d + 10240, Abl + off, 16);
        }
        if (!bTrans) {
            int row = tid >> 2, ks = (tid & 3) << 2;
            int n = n0 + row;
            unsigned sz = (n < N) ? 16u : 0u;
            size_t off = (size_t)(n < N ? n : 0) * ldb + kt + ks;
            unsigned d = sb + 20480 + (unsigned)(row * TPB + ks) * 4;
            cpa16(d,        Bbh + off, sz);
            cpa16(d + 5120, Bbl + off, sz);
        } else {
            int k = tid >> 4, ns = (tid & 15) << 2;
            size_t off = (size_t)(kt + k) * ldb + n0 + ns;
            unsigned d = sb + 20480 + (unsigned)(k * TPN + ns) * 4;
            cpa16(d,        Bbh + off, 16);
            cpa16(d + 5120, Bbl + off, 16);
        }
        asm volatile("cp.async.commit_group;");
    };

    const int nt = K >> 4;
    load_stage(0, 0);
    int buf = 0;

    for (int it = 0; it < nt; it++) {
        if (it + 1 < nt) {
            load_stage(buf ^ 1, (it + 1) << 4);
            asm volatile("cp.async.wait_group 1;");
        } else {
            asm volatile("cp.async.wait_group 0;");
        }
        __syncthreads();

        const float* Ah = smf + buf * 7680;
        const float* Al = Ah + 2560;
        const float* Bh = Ah + 5120;
        const float* Bl = Ah + 6400;

        #pragma unroll
        for (int k8 = 0; k8 < 16; k8 += 8) {
            unsigned ah[2][4], al[2][4], bh[4][2], bl[4][2];
            #pragma unroll
            for (int ta = 0; ta < 2; ta++) {
                int base = (wm * 32 + ta * 16 + gq) * TPB + k8 + tig;
                ah[ta][0] = __float_as_uint(Ah[base]);
                ah[ta][1] = __float_as_uint(Ah[base + 8 * TPB]);
                ah[ta][2] = __float_as_uint(Ah[base + 4]);
                ah[ta][3] = __float_as_uint(Ah[base + 8 * TPB + 4]);
                al[ta][0] = __float_as_uint(Al[base]);
                al[ta][1] = __float_as_uint(Al[base + 8 * TPB]);
                al[ta][2] = __float_as_uint(Al[base + 4]);
                al[ta][3] = __float_as_uint(Al[base + 8 * TPB + 4]);
            }
            #pragma unroll
            for (int tb = 0; tb < 4; tb++) {
                if (!bTrans) {
                    int base = (wn * 32 + tb * 8 + gq) * TPB + k8 + tig;
                    bh[tb][0] = __float_as_uint(Bh[base]);
                    bh[tb][1] = __float_as_uint(Bh[base + 4]);
                    bl[tb][0] = __float_as_uint(Bl[base]);
                    bl[tb][1] = __float_as_uint(Bl[base + 4]);
                } else {
                    int base = (k8 + tig) * TPN + wn * 32 + tb * 8 + gq;
                    bh[tb][0] = __float_as_uint(Bh[base]);
                    bh[tb][1] = __float_as_uint(Bh[base + 4 * TPN]);
                    bl[tb][0] = __float_as_uint(Bl[base]);
                    bl[tb][1] = __float_as_uint(Bl[base + 4 * TPN]);
                }
            }
            #pragma unroll
            for (int ta = 0; ta < 2; ta++)
                #pragma unroll
                for (int tb = 0; tb < 4; tb++) {
                    float* cc = c[ta][tb];
                    asm volatile(
                        "mma.sync.aligned.m16n8k8.row.col.f32.tf32.tf32.f32 "
                        "{%0,%1,%2,%3}, {%4,%5,%6,%7}, {%8,%9}, {%0,%1,%2,%3};"
                        : "+f"(cc[0]), "+f"(cc[1]), "+f"(cc[2]), "+f"(cc[3])
                        : "r"(ah[ta][0]), "r"(ah[ta][1]), "r"(ah[ta][2]), "r"(ah[ta][3]),
                          "r"(bh[tb][0]), "r"(bh[tb][1]));
                    asm volatile(
                        "mma.sync.aligned.m16n8k8.row.col.f32.tf32.tf32.f32 "
                        "{%0,%1,%2,%3}, {%4,%5,%6,%7}, {%8,%9}, {%0,%1,%2,%3};"
                        : "+f"(cc[0]), "+f"(cc[1]), "+f"(cc[2]), "+f"(cc[3])
                        : "r"(ah[ta][0]), "r"(ah[ta][1]), "r"(ah[ta][2]), "r"(ah[ta][3]),
                          "r"(bl[tb][0]), "r"(bl[tb][1]));
                    asm volatile(
                        "mma.sync.aligned.m16n8k8.row.col.f32.tf32.tf32.f32 "
                        "{%0,%1,%2,%3}, {%4,%5,%6,%7}, {%8,%9}, {%0,%1,%2,%3};"
                        : "+f"(cc[0]), "+f"(cc[1]), "+f"(cc[2]), "+f"(cc[3])
                        : "r"(al[ta][0]), "r"(al[ta][1]), "r"(al[ta][2]), "r"(al[ta][3]),
                          "r"(bh[tb][0]), "r"(bh[tb][1]));
                }
        }
        __syncthreads();
        buf ^= 1;
    }

    float* Cb  = C  ? C  + (long long)blockIdx.z * cBS : (float*)0;
    float* Chb = Ch ? Ch + (long long)blockIdx.z * cBS : (float*)0;
    float* Clb = Cl ? Cl + (long long)blockIdx.z * cBS : (float*)0;

    #pragma unroll
    for (int ta = 0; ta < 2; ta++) {
        int mrow = m0 + wm * 32 + ta * 16 + gq;
        #pragma unroll
        for (int tb = 0; tb < 4; tb++) {
            int ncol = n0 + wn * 32 + tb * 8 + 2 * tig;
            #pragma unroll
            for (int half = 0; half < 2; half++) {
                int m = mrow + half * 8;
                #pragma unroll
                for (int q = 0; q < 2; q++) {
                    int n = ncol + q;
                    if (n < N) {
                        float v = c[ta][tb][half * 2 + q];
                        if (bias1) v += bias1[n];
                        if (bias2) v += bias2[n];
                        size_t idx = transC
                            ? ((size_t)(m >> 5) * G4 + n) * BB + (m & 31)
                            : (size_t)m * ldc + n;
                        if (Cb) Cb[idx] = v;
                        if (Chb) {
                            float hh = tf32r(v);
                            Chb[idx] = hh;
                            Clb[idx] = tf32r(v - hh);
                        }
                    }
                }
            }
        }
    }
}

// ---------------- online softmax (2 passes) in place ----------------
__global__ __launch_bounds__(256)
void softmax_rows(float* __restrict__ data, int L)
{
    float* p = data + (size_t)blockIdx.x * L;
    __shared__ float rm[256], rs[256];
    const int tid = threadIdx.x;

    // pass 1: online max+sum
    float m = -3.4e38f, s = 0.f;
    for (int i = tid; i < L; i += 256) {
        float v = p[i];
        if (v > m) { s = s * expf(m - v) + 1.f; m = v; }
        else       { s += expf(v - m); }
    }
    rm[tid] = m; rs[tid] = s; __syncthreads();
    #pragma unroll
    for (int st = 128; st > 0; st >>= 1) {
        if (tid < st) {
            float m2 = rm[tid + st], s2 = rs[tid + st];
            float m1 = rm[tid],      s1 = rs[tid];
            float mm = fmaxf(m1, m2);
            rm[tid] = mm;
            rs[tid] = s1 * expf(m1 - mm) + s2 * expf(m2 - mm);
        }
        __syncthreads();
    }
    m = rm[0];
    const float inv = 1.f / rs[0];

    // pass 2: write
    for (int i = tid; i < L; i += 256)
        p[i] = expf(p[i] - m) * inv;
}

// ---------------- softmax + tf32 split output (R13) ----------------
__global__ __launch_bounds__(256)
void softmax_split(const float* __restrict__ in,
                   float* __restrict__ oh, float* __restrict__ ol, int L)
{
    const float* p = in + (size_t)blockIdx.x * L;
    float* ph = oh + (size_t)blockIdx.x * L;
    float* pl = ol + (size_t)blockIdx.x * L;
    __shared__ float red[256];
    const int tid = threadIdx.x;

    float m = -3.4e38f;
    for (int i = tid; i < L; i += 256) m = fmaxf(m, p[i]);
    red[tid] = m; __syncthreads();
    #pragma unroll
    for (int s = 128; s > 0; s >>= 1) {
        if (tid < s) red[tid] = fmaxf(red[tid], red[tid + s]);
        __syncthreads();
    }
    m = red[0]; __syncthreads();

    float sum = 0.f;
    for (int i = tid; i < L; i += 256) sum += expf(p[i] - m);
    red[tid] = sum; __syncthreads();
    #pragma unroll
    for (int s = 128; s > 0; s >>= 1) {
        if (tid < s) red[tid] += red[tid + s];
        __syncthreads();
    }
    const float inv = 1.f / red[0];
    for (int i = tid; i < L; i += 256) {
        float w = expf(p[i] - m) * inv;
        float hh = tf32r(w);
        ph[i] = hh;
        pl[i] = tf32r(w - hh);
    }
}

// ---------------- launch ----------------
extern "C" void kernel_launch(void* const* d_in, const int* in_sizes, int n_in,
                              void* d_out, int out_size)
{
    const float* inputs = (const float*)d_in[0];
    const float* h0     = (const float*)d_in[1];
    const float* c0     = (const float*)d_in[2];
    const float* Lst    = (const float*)d_in[3];
    const float* W_ih1  = (const float*)d_in[4];
    const float* W_hh1  = (const float*)d_in[5];
    const float* b_ih1  = (const float*)d_in[6];
    const float* b_hh1  = (const float*)d_in[7];
    const float* W_ih2  = (const float*)d_in[8];
    const float* W_hh2  = (const float*)d_in[9];
    const float* b_ih2  = (const float*)d_in[10];
    const float* b_hh2  = (const float*)d_in[11];
    const float* W_out  = (const float*)d_in[12];
    const float* b_out  = (const float*)d_in[13];
    float* out = (float*)d_out;

    void* p;
    cudaGetSymbolAddress(&p, g_X1);  float* X1  = (float*)p;
    cudaGetSymbolAddress(&p, g_X2);  float* X2  = (float*)p;
    cudaGetSymbolAddress(&p, g_S);   float* S   = (float*)p;
    cudaGetSymbolAddress(&p, g_INh); float* INh = (float*)p;
    cudaGetSymbolAddress(&p, g_INl); float* INl = (float*)p;
    cudaGetSymbolAddress(&p, g_W1h); float* W1h = (float*)p;
    cudaGetSymbolAddress(&p, g_W1l); float* W1l = (float*)p;
    cudaGetSymbolAddress(&p, g_W2h); float* W2h = (float*)p;
    cudaGetSymbolAddress(&p, g_W2l); float* W2l = (float*)p;
    cudaGetSymbolAddress(&p, g_WOh); float* WOh = (float*)p;
    cudaGetSymbolAddress(&p, g_WOl); float* WOl = (float*)p;
    cudaGetSymbolAddress(&p, g_Lh);  float* Lh  = (float*)p;
    cudaGetSymbolAddress(&p, g_Ll);  float* Ll  = (float*)p;
    cudaGetSymbolAddress(&p, g_H1h); float* H1h = (float*)p;
    cudaGetSymbolAddress(&p, g_H1l); float* H1l = (float*)p;
    cudaGetSymbolAddress(&p, g_Sh);  float* Sh  = (float*)p;
    cudaGetSymbolAddress(&p, g_Sl);  float* Sl  = (float*)p;
    cudaGetSymbolAddress(&p, g_CXh); float* CXh = (float*)p;
    cudaGetSymbolAddress(&p, g_CXl); float* CXl = (float*)p;
    cudaGetSymbolAddress(&p, g_HSh); float* HSh = (float*)p;
    cudaGetSymbolAddress(&p, g_HSl); float* HSl = (float*)p;

    cudaFuncSetAttribute(lstm_seq, cudaFuncAttributeMaxDynamicSharedMemorySize,
                         SMEM_LSTM);
    cudaFuncSetAttribute(gemm_v3, cudaFuncAttributeMaxDynamicSharedMemorySize,
                         SMEM_GEMM);

    // operand splits
    split_tf32<<<TT*BB*EE/1024, 256>>>((const float4*)inputs, (float4*)INh, (float4*)INl);
    split_tf32<<<G4*EE/1024,   256>>>((const float4*)W_ih1, (float4*)W1h, (float4*)W1l);
    split_tf32<<<G4*HH/1024,   256>>>((const float4*)W_ih2, (float4*)W2h, (float4*)W2l);
    split_tf32<<<VV*HH/1024,   256>>>((const float4*)W_out, (float4*)WOh, (float4*)WOl);
    split_tf32<<<UU*BB*HH/1024,256>>>((const float4*)Lst,   (float4*)Lh,  (float4*)Ll);

    // X1 = inputs @ W_ih1^T + biases -> [t][g4][b]
    {
        dim3 g(G4 / 64, (TT * BB) / 128, 1);
        gemm_v3<<<g, 256, SMEM_GEMM>>>(INh, INl, W1h, W1l, X1, 0, 0,
                                       b_ih1, b_hh1,
                                       TT * BB, G4, EE, EE, EE, G4,
                                       0, 0, 0, 1, 0);
    }

    // layer-1 recurrence -> H1 hi/lo
    prep<<<1, 256>>>(h0);
    lstm_seq<<<NBLK, 256, SMEM_LSTM>>>(X1, W_hh1, c0, H1h, H1l);

    // S = H1 @ L^T (batched)
    {
        dim3 g(UU / 64, 1, BB);
        gemm_v3<<<g, 256, SMEM_GEMM>>>(H1h, H1l, Lh, Ll, S, 0, 0,
                                       0, 0,
                                       TT, UU, HH, BB * HH, BB * HH, BB * UU,
                                       HH, HH, UU, 0, 0);
    }
    softmax_split<<<TT * BB, 256>>>(S, Sh, Sl, UU);

    // CTX = softmax(S) @ L (NN), epilogue writes tf32 hi/lo
    {
        dim3 g(HH / 64, 1, BB);
        gemm_v3<<<g, 256, SMEM_GEMM>>>(Sh, Sl, Lh, Ll, 0, CXh, CXl,
                                       0, 0,
                                       TT, HH, UU, BB * UU, BB * HH, BB * HH,
                                       UU, HH, HH, 0, 1);
    }

    // X2 = CTX @ W_ih2^T + biases -> [t][g4][b]
    {
        dim3 g(G4 / 64, (TT * BB) / 128, 1);
        gemm_v3<<<g, 256, SMEM_GEMM>>>(CXh, CXl, W2h, W2l, X2, 0, 0,
                                       b_ih2, b_hh2,
                                       TT * BB, G4, HH, HH, HH, G4,
                                       0, 0, 0, 1, 0);
    }

    // layer-2 recurrence -> HS hi/lo
    prep<<<1, 256>>>(h0 + BB * HH);
    lstm_seq<<<NBLK, 256, SMEM_LSTM>>>(X2, W_hh2, c0 + BB * HH, HSh, HSl);

    // logits = HS @ W_out^T + b_out -> softmax over V
    {
        dim3 g((VV + 63) / 64, (TT * BB) / 128, 1);
        gemm_v3<<<g, 256, SMEM_GEMM>>>(HSh, HSl, WOh, WOl, out, 0, 0,
                                       b_out, 0,
                                       TT * BB, VV, HH, HH, HH, VV,
                                       0, 0, 0, 0, 0);
    }
    softmax_rows<<<TT * BB, 256>>>(out, VV);
}

// round 16
// speedup vs baseline: 1.8060x; 1.1377x over previous
#include <cuda_runtime.h>
#include <math.h>

#define TT 128
#define BB 32
#define EE 512
#define HH 512
#define UU 1024
#define VV 10000
#define G4 2048   // 4*H

#define NBLK 128
#define SMEM_LSTM (131072 + 32768 + 16384)   // Wt + hsd + Pp = 176KB
#define SMEM_GEMM 61440                      // 2 stages x 30720B

// ---------------- scratch (static device globals; no allocation) ----------------
__device__ __align__(128) float g_X1 [TT*G4*BB];   // pregates [t][g4][b]
__device__ __align__(128) float g_X2 [TT*G4*BB];
__device__ __align__(128) float g_S  [TT*BB*UU];   // fp32 scores
// tf32 hi/lo operand buffers
__device__ __align__(128) float g_INh[TT*BB*EE],  g_INl[TT*BB*EE];
__device__ __align__(128) float g_W1h[G4*EE],     g_W1l[G4*EE];
__device__ __align__(128) float g_W2h[G4*HH],     g_W2l[G4*HH];
__device__ __align__(128) float g_WOh[VV*HH],     g_WOl[VV*HH];
__device__ __align__(128) float g_Lh [UU*BB*HH],  g_Ll [UU*BB*HH];
__device__ __align__(128) float g_H1h[TT*BB*HH],  g_H1l[TT*BB*HH];
__device__ __align__(128) float g_Sh [TT*BB*UU],  g_Sl [TT*BB*UU];
__device__ __align__(128) float g_CXh[TT*BB*HH],  g_CXl[TT*BB*HH];
__device__ __align__(128) float g_HSh[TT*BB*HH],  g_HSl[TT*BB*HH];
__device__ __align__(128) float g_HT [2][4*512*8]; // parity h [bg][k][b8]
__device__ unsigned g_flag[NBLK];

// ---------------- helpers ----------------
typedef unsigned long long ull;
__device__ __forceinline__ ull pack2(float x) {
    ull r;
    asm("mov.b64 %0, {%1, %1};" : "=l"(r) : "r"(__float_as_uint(x)));
    return r;
}
__device__ __forceinline__ void fma2(ull& d, ull a, ull b) {
    asm("fma.rn.f32x2 %0, %1, %2, %0;" : "+l"(d) : "l"(a), "l"(b));
}
__device__ __forceinline__ unsigned ld_acq(const unsigned* p) {
    unsigned v;
    asm volatile("ld.acquire.gpu.global.u32 %0, [%1];" : "=r"(v) : "l"(p));
    return v;
}
__device__ __forceinline__ void st_rel(unsigned* p, unsigned v) {
    asm volatile("st.release.gpu.global.u32 [%0], %1;" :: "l"(p), "r"(v) : "memory");
}
__device__ __forceinline__ float sigmoidf_(float x) { return 1.f / (1.f + expf(-x)); }
__device__ __forceinline__ float tf32r(float f) {
    unsigned u;
    asm("cvt.rna.tf32.f32 %0, %1;" : "=r"(u) : "f"(f));
    return __uint_as_float(u);
}
__device__ __forceinline__ unsigned smem_u32(const void* p) {
    unsigned a;
    asm("{ .reg .u64 t; cvta.to.shared.u64 t, %1; cvt.u32.u64 %0, t; }"
        : "=r"(a) : "l"(p));
    return a;
}
__device__ __forceinline__ void cpa16(unsigned dst, const void* src, unsigned sz) {
    asm volatile("cp.async.cg.shared.global [%0], [%1], 16, %2;"
                 :: "r"(dst), "l"(src), "r"(sz));
}

// ---------------- tf32 hi/lo split (elementwise, float4) ----------------
__global__ void split_tf32(const float4* __restrict__ src,
                           float4* __restrict__ hi, float4* __restrict__ lo)
{
    int i = blockIdx.x * 256 + threadIdx.x;
    float4 v = src[i], h, l;
    h.x = tf32r(v.x); l.x = tf32r(v.x - h.x);
    h.y = tf32r(v.y); l.y = tf32r(v.y - h.y);
    h.z = tf32r(v.z); l.z = tf32r(v.z - h.z);
    h.w = tf32r(v.w); l.w = tf32r(v.w - h.w);
    hi[i] = h; lo[i] = l;
}

// ---------------- prep: reset flags, h0 -> g_HT[1] ----------------
__global__ void prep(const float* __restrict__ h0row)
{
    int tid = threadIdx.x;
    if (tid < NBLK) g_flag[tid] = 0;
    for (int idx = tid; idx < BB * HH; idx += 256) {
        int b = idx >> 9, h = idx & 511;
        g_HT[1][(b >> 3) * 4096 + h * 8 + (b & 7)] = h0row[idx];
    }
}

// ---------------- persistent LSTM recurrence (R13, frozen) ----------------------
__global__ __launch_bounds__(256)
void lstm_seq(const float* __restrict__ XT,     // [T][G4][B] pregates
              const float* __restrict__ Whh,    // [G4][H]
              const float* __restrict__ c0row,  // [B][H]
              float* __restrict__ Hh,           // [T][B][H] tf32-hi
              float* __restrict__ Hl)           // [T][B][H] tf32-lo
{
    extern __shared__ char smraw[];
    float* Wt  = (float*)smraw;                   // [512][64]
    ull*   hsd = (ull*)(smraw + 131072);          // [512][8]
    ull*   Pp  = (ull*)(smraw + 131072 + 32768);  // [8][32][8]

    const int bid = blockIdx.x;
    const int tid = threadIdx.x;
    const int hc  = bid & 31;
    const int bg  = bid >> 5;

    for (int idx = tid; idx < 64 * 128; idx += 256) {
        int r  = idx & 63;
        int k4 = idx >> 6;
        int g = r >> 4, j = r & 15;
        int gr = g * 512 + 16 * hc + j;
        float4 w = *(const float4*)(Whh + (size_t)gr * HH + k4 * 4);
        Wt[(k4 * 4 + 0) * 64 + r] = w.x;
        Wt[(k4 * 4 + 1) * 64 + r] = w.y;
        Wt[(k4 * 4 + 2) * 64 + r] = w.z;
        Wt[(k4 * 4 + 3) * 64 + r] = w.w;
    }

    const int warp = tid >> 5;
    const int lane = tid & 31;
    const int rg   = lane >> 1;
    const int bq   = lane & 1;
    const int kbeg = warp * 64;

    const int j  = tid >> 3;
    const int bb = tid & 7;
    float cv = 0.f;
    if (tid < 128) cv = c0row[(8 * bg + bb) * HH + 16 * hc + j];

    unsigned* myflag = &g_flag[bid];
    const unsigned* grpflags = &g_flag[bg * 32];

    for (int t = 0; t < TT; t++) {
        if (t > 0) {
            if (tid < 32) {
                const unsigned* f = grpflags + tid;
                while (ld_acq(f) < (unsigned)t) { }
            }
        }
        __syncthreads();

        {
            const float4* src = (const float4*)&g_HT[(t + 1) & 1][bg * 4096];
            #pragma unroll
            for (int r = 0; r < 4; r++) {
                int i = tid + r * 256;
                float4 v = __ldcg(src + i);
                int k  = i >> 1;
                int b0 = (i & 1) * 4;
                ull* d = &hsd[k * 8 + b0];
                d[0] = pack2(v.x); d[1] = pack2(v.y);
                d[2] = pack2(v.z); d[3] = pack2(v.w);
            }
        }

        float xg0 = 0.f, xg1 = 0.f, xg2 = 0.f, xg3 = 0.f;
        if (tid < 128) {
            const float* xb = XT + ((size_t)t * G4 + 16 * hc + j) * BB
                              + 8 * bg + bb;
            xg0 = __ldcg(xb);
            xg1 = __ldcg(xb + (size_t)512  * BB);
            xg2 = __ldcg(xb + (size_t)1024 * BB);
            xg3 = __ldcg(xb + (size_t)1536 * BB);
        }
        __syncthreads();

        ull acc[2][4];
        #pragma unroll
        for (int i = 0; i < 2; i++)
            #pragma unroll
            for (int q = 0; q < 4; q++) acc[i][q] = 0ull;

        #pragma unroll 4
        for (int k = kbeg; k < kbeg + 64; k++) {
            ulonglong2 wp = *(const ulonglong2*)&Wt[k * 64 + rg * 4];
            ulonglong2 hA = *(const ulonglong2*)&hsd[k * 8 + bq * 4];
            ulonglong2 hB = *(const ulonglong2*)&hsd[k * 8 + bq * 4 + 2];
            fma2(acc[0][0], wp.x, hA.x); fma2(acc[0][1], wp.x, hA.y);
            fma2(acc[0][2], wp.x, hB.x); fma2(acc[0][3], wp.x, hB.y);
            fma2(acc[1][0], wp.y, hA.x); fma2(acc[1][1], wp.y, hA.y);
            fma2(acc[1][2], wp.y, hB.x); fma2(acc[1][3], wp.y, hB.y);
        }

        {
            ull* pb = &Pp[((warp * 32) + rg * 2) * 8 + bq * 4];
            *(ulonglong2*)(pb + 0)  = make_ulonglong2(acc[0][0], acc[0][1]);
            *(ulonglong2*)(pb + 2)  = make_ulonglong2(acc[0][2], acc[0][3]);
            *(ulonglong2*)(pb + 8)  = make_ulonglong2(acc[1][0], acc[1][1]);
            *(ulonglong2*)(pb + 10) = make_ulonglong2(acc[1][2], acc[1][3]);
        }
        __syncthreads();

        float hv = 0.f;
        if (tid < 128) {
            const float* pf = (const float*)Pp;
            float gv[4] = {xg0, xg1, xg2, xg3};
            #pragma unroll
            for (int g = 0; g < 4; g++) {
                int r  = g * 16 + j;
                int rp = r >> 1, ln = r & 1;
                float s = 0.f;
                #pragma unroll
                for (int sI = 0; sI < 8; sI++)
                    s += pf[((sI * 32 + rp) * 8 + bb) * 2 + ln];
                gv[g] += s;
            }
            float gi = sigmoidf_(gv[0]);
            float gf = sigmoidf_(gv[1]);
            float gg = tanhf(gv[2]);
            float go = sigmoidf_(gv[3]);
            cv = gf * cv + gi * gg;
            hv = go * tanhf(cv);
            g_HT[t & 1][bg * 4096 + (16 * hc + j) * 8 + bb] = hv;
        }

        __syncthreads();
        if (tid == 0) st_rel(myflag, (unsigned)(t + 1));
        if (tid < 128) {
            size_t idx = (size_t)t * BB * HH + (8 * bg + bb) * HH + 16 * hc + j;
            float hh = tf32r(hv);
            Hh[idx] = hh;
            Hl[idx] = tf32r(hv - hh);
        }
    }
}

// ---------------- tf32x3 tensor GEMM v3 (R13, frozen) ---------------------------
#define TPB 20
#define TPN 72
__global__ __launch_bounds__(256)
void gemm_v3(const float* __restrict__ Ahg, const float* __restrict__ Alg,
             const float* __restrict__ Bhg, const float* __restrict__ Blg,
             float* __restrict__ C, float* __restrict__ Ch, float* __restrict__ Cl,
             const float* __restrict__ bias1, const float* __restrict__ bias2,
             int M, int N, int K, int lda, int ldb, int ldc,
             long long aBS, long long bBS, long long cBS,
             int transC, int bTrans)
{
    extern __shared__ float smf[];
    const unsigned sbase = smem_u32(smf);

    const int tid  = threadIdx.x;
    const int warp = tid >> 5;
    const int lane = tid & 31;
    const int wm = warp >> 1;
    const int wn = warp & 1;
    const int gq  = lane >> 2;
    const int tig = lane & 3;

    const int m0 = blockIdx.y * 128;
    const int n0 = blockIdx.x * 64;

    const float* Abh = Ahg + (long long)blockIdx.z * aBS;
    const float* Abl = Alg + (long long)blockIdx.z * aBS;
    const float* Bbh = Bhg + (long long)blockIdx.z * bBS;
    const float* Bbl = Blg + (long long)blockIdx.z * bBS;

    float c[2][4][4];
    #pragma unroll
    for (int ta = 0; ta < 2; ta++)
        #pragma unroll
        for (int tb = 0; tb < 4; tb++)
            #pragma unroll
            for (int q = 0; q < 4; q++) c[ta][tb][q] = 0.f;

    auto load_stage = [&](int s, int kt) {
        unsigned sb = sbase + s * 30720;
        #pragma unroll
        for (int r = 0; r < 2; r++) {
            int sgi = tid + r * 256;
            int row = sgi >> 2, ks = (sgi & 3) << 2;
            size_t off = (size_t)(m0 + row) * lda + kt + ks;
            unsigned d = sb + (unsigned)(row * TPB + ks) * 4;
            cpa16(d,         Abh + off, 16);
            cpa16(d + 10240, Abl + off, 16);
        }
        if (!bTrans) {
            int row = tid >> 2, ks = (tid & 3) << 2;
            int n = n0 + row;
            unsigned sz = (n < N) ? 16u : 0u;
            size_t off = (size_t)(n < N ? n : 0) * ldb + kt + ks;
            unsigned d = sb + 20480 + (unsigned)(row * TPB + ks) * 4;
            cpa16(d,        Bbh + off, sz);
            cpa16(d + 5120, Bbl + off, sz);
        } else {
            int k = tid >> 4, ns = (tid & 15) << 2;
            size_t off = (size_t)(kt + k) * ldb + n0 + ns;
            unsigned d = sb + 20480 + (unsigned)(k * TPN + ns) * 4;
            cpa16(d,        Bbh + off, 16);
            cpa16(d + 5120, Bbl + off, 16);
        }
        asm volatile("cp.async.commit_group;");
    };

    const int nt = K >> 4;
    load_stage(0, 0);
    int buf = 0;

    for (int it = 0; it < nt; it++) {
        if (it + 1 < nt) {
            load_stage(buf ^ 1, (it + 1) << 4);
            asm volatile("cp.async.wait_group 1;");
        } else {
            asm volatile("cp.async.wait_group 0;");
        }
        __syncthreads();

        const float* Ah = smf + buf * 7680;
        const float* Al = Ah + 2560;
        const float* Bh = Ah + 5120;
        const float* Bl = Ah + 6400;

        #pragma unroll
        for (int k8 = 0; k8 < 16; k8 += 8) {
            unsigned ah[2][4], al[2][4], bh[4][2], bl[4][2];
            #pragma unroll
            for (int ta = 0; ta < 2; ta++) {
                int base = (wm * 32 + ta * 16 + gq) * TPB + k8 + tig;
                ah[ta][0] = __float_as_uint(Ah[base]);
                ah[ta][1] = __float_as_uint(Ah[base + 8 * TPB]);
                ah[ta][2] = __float_as_uint(Ah[base + 4]);
                ah[ta][3] = __float_as_uint(Ah[base + 8 * TPB + 4]);
                al[ta][0] = __float_as_uint(Al[base]);
                al[ta][1] = __float_as_uint(Al[base + 8 * TPB]);
                al[ta][2] = __float_as_uint(Al[base + 4]);
                al[ta][3] = __float_as_uint(Al[base + 8 * TPB + 4]);
            }
            #pragma unroll
            for (int tb = 0; tb < 4; tb++) {
                if (!bTrans) {
                    int base = (wn * 32 + tb * 8 + gq) * TPB + k8 + tig;
                    bh[tb][0] = __float_as_uint(Bh[base]);
                    bh[tb][1] = __float_as_uint(Bh[base + 4]);
                    bl[tb][0] = __float_as_uint(Bl[base]);
                    bl[tb][1] = __float_as_uint(Bl[base + 4]);
                } else {
                    int base = (k8 + tig) * TPN + wn * 32 + tb * 8 + gq;
                    bh[tb][0] = __float_as_uint(Bh[base]);
                    bh[tb][1] = __float_as_uint(Bh[base + 4 * TPN]);
                    bl[tb][0] = __float_as_uint(Bl[base]);
                    bl[tb][1] = __float_as_uint(Bl[base + 4 * TPN]);
                }
            }
            #pragma unroll
            for (int ta = 0; ta < 2; ta++)
                #pragma unroll
                for (int tb = 0; tb < 4; tb++) {
                    float* cc = c[ta][tb];
                    asm volatile(
                        "mma.sync.aligned.m16n8k8.row.col.f32.tf32.tf32.f32 "
                        "{%0,%1,%2,%3}, {%4,%5,%6,%7}, {%8,%9}, {%0,%1,%2,%3};"
                        : "+f"(cc[0]), "+f"(cc[1]), "+f"(cc[2]), "+f"(cc[3])
                        : "r"(ah[ta][0]), "r"(ah[ta][1]), "r"(ah[ta][2]), "r"(ah[ta][3]),
                          "r"(bh[tb][0]), "r"(bh[tb][1]));
                    asm volatile(
                        "mma.sync.aligned.m16n8k8.row.col.f32.tf32.tf32.f32 "
                        "{%0,%1,%2,%3}, {%4,%5,%6,%7}, {%8,%9}, {%0,%1,%2,%3};"
                        : "+f"(cc[0]), "+f"(cc[1]), "+f"(cc[2]), "+f"(cc[3])
                        : "r"(ah[ta][0]), "r"(ah[ta][1]), "r"(ah[ta][2]), "r"(ah[ta][3]),
                          "r"(bl[tb][0]), "r"(bl[tb][1]));
                    asm volatile(
                        "mma.sync.aligned.m16n8k8.row.col.f32.tf32.tf32.f32 "
                        "{%0,%1,%2,%3}, {%4,%5,%6,%7}, {%8,%9}, {%0,%1,%2,%3};"
                        : "+f"(cc[0]), "+f"(cc[1]), "+f"(cc[2]), "+f"(cc[3])
                        : "r"(al[ta][0]), "r"(al[ta][1]), "r"(al[ta][2]), "r"(al[ta][3]),
                          "r"(bh[tb][0]), "r"(bh[tb][1]));
                }
        }
        __syncthreads();
        buf ^= 1;
    }

    float* Cb  = C  ? C  + (long long)blockIdx.z * cBS : (float*)0;
    float* Chb = Ch ? Ch + (long long)blockIdx.z * cBS : (float*)0;
    float* Clb = Cl ? Cl + (long long)blockIdx.z * cBS : (float*)0;

    #pragma unroll
    for (int ta = 0; ta < 2; ta++) {
        int mrow = m0 + wm * 32 + ta * 16 + gq;
        #pragma unroll
        for (int tb = 0; tb < 4; tb++) {
            int ncol = n0 + wn * 32 + tb * 8 + 2 * tig;
            #pragma unroll
            for (int half = 0; half < 2; half++) {
                int m = mrow + half * 8;
                #pragma unroll
                for (int q = 0; q < 2; q++) {
                    int n = ncol + q;
                    if (n < N) {
                        float v = c[ta][tb][half * 2 + q];
                        if (bias1) v += bias1[n];
                        if (bias2) v += bias2[n];
                        size_t idx = transC
                            ? ((size_t)(m >> 5) * G4 + n) * BB + (m & 31)
                            : (size_t)m * ldc + n;
                        if (Cb) Cb[idx] = v;
                        if (Chb) {
                            float hh = tf32r(v);
                            Chb[idx] = hh;
                            Clb[idx] = tf32r(v - hh);
                        }
                    }
                }
            }
        }
    }
}

// ---------------- online softmax (fused max+sum pass, then normalize) -----------
__global__ __launch_bounds__(256)
void softmax_rows(float* __restrict__ data, int L)
{
    float* p = data + (size_t)blockIdx.x * L;
    __shared__ float rm[256], rs[256];
    const int tid = threadIdx.x;

    float m = -3.4e38f, s = 0.f;
    for (int i = tid; i < L; i += 256) {
        float v = p[i];
        if (v > m) { s = s * expf(m - v) + 1.f; m = v; }
        else       { s += expf(v - m); }
    }
    rm[tid] = m; rs[tid] = s; __syncthreads();
    #pragma unroll
    for (int st = 128; st > 0; st >>= 1) {
        if (tid < st) {
            float m2 = rm[tid + st], s2 = rs[tid + st];
            float m1 = rm[tid],      s1 = rs[tid];
            float mm = fmaxf(m1, m2);
            rm[tid] = mm;
            rs[tid] = s1 * expf(m1 - mm) + s2 * expf(m2 - mm);
        }
        __syncthreads();
    }
    m = rm[0];
    const float inv = 1.f / rs[0];

    for (int i = tid; i < L; i += 256)
        p[i] = expf(p[i] - m) * inv;
}

// ---------------- softmax + tf32 split output (R13, frozen) ----------------
__global__ __launch_bounds__(256)
void softmax_split(const float* __restrict__ in,
                   float* __restrict__ oh, float* __restrict__ ol, int L)
{
    const float* p = in + (size_t)blockIdx.x * L;
    float* ph = oh + (size_t)blockIdx.x * L;
    float* pl = ol + (size_t)blockIdx.x * L;
    __shared__ float red[256];
    const int tid = threadIdx.x;

    float m = -3.4e38f;
    for (int i = tid; i < L; i += 256) m = fmaxf(m, p[i]);
    red[tid] = m; __syncthreads();
    #pragma unroll
    for (int s = 128; s > 0; s >>= 1) {
        if (tid < s) red[tid] = fmaxf(red[tid], red[tid + s]);
        __syncthreads();
    }
    m = red[0]; __syncthreads();

    float sum = 0.f;
    for (int i = tid; i < L; i += 256) sum += expf(p[i] - m);
    red[tid] = sum; __syncthreads();
    #pragma unroll
    for (int s = 128; s > 0; s >>= 1) {
        if (tid < s) red[tid] += red[tid + s];
        __syncthreads();
    }
    const float inv = 1.f / red[0];
    for (int i = tid; i < L; i += 256) {
        float w = expf(p[i] - m) * inv;
        float hh = tf32r(w);
        ph[i] = hh;
        pl[i] = tf32r(w - hh);
    }
}

// ---------------- launch ----------------
extern "C" void kernel_launch(void* const* d_in, const int* in_sizes, int n_in,
                              void* d_out, int out_size)
{
    const float* inputs = (const float*)d_in[0];
    const float* h0     = (const float*)d_in[1];
    const float* c0     = (const float*)d_in[2];
    const float* Lst    = (const float*)d_in[3];
    const float* W_ih1  = (const float*)d_in[4];
    const float* W_hh1  = (const float*)d_in[5];
    const float* b_ih1  = (const float*)d_in[6];
    const float* b_hh1  = (const float*)d_in[7];
    const float* W_ih2  = (const float*)d_in[8];
    const float* W_hh2  = (const float*)d_in[9];
    const float* b_ih2  = (const float*)d_in[10];
    const float* b_hh2  = (const float*)d_in[11];
    const float* W_out  = (const float*)d_in[12];
    const float* b_out  = (const float*)d_in[13];
    float* out = (float*)d_out;

    void* p;
    cudaGetSymbolAddress(&p, g_X1);  float* X1  = (float*)p;
    cudaGetSymbolAddress(&p, g_X2);  float* X2  = (float*)p;
    cudaGetSymbolAddress(&p, g_S);   float* S   = (float*)p;
    cudaGetSymbolAddress(&p, g_INh); float* INh = (float*)p;
    cudaGetSymbolAddress(&p, g_INl); float* INl = (float*)p;
    cudaGetSymbolAddress(&p, g_W1h); float* W1h = (float*)p;
    cudaGetSymbolAddress(&p, g_W1l); float* W1l = (float*)p;
    cudaGetSymbolAddress(&p, g_W2h); float* W2h = (float*)p;
    cudaGetSymbolAddress(&p, g_W2l); float* W2l = (float*)p;
    cudaGetSymbolAddress(&p, g_WOh); float* WOh = (float*)p;
    cudaGetSymbolAddress(&p, g_WOl); float* WOl = (float*)p;
    cudaGetSymbolAddress(&p, g_Lh);  float* Lh  = (float*)p;
    cudaGetSymbolAddress(&p, g_Ll);  float* Ll  = (float*)p;
    cudaGetSymbolAddress(&p, g_H1h); float* H1h = (float*)p;
    cudaGetSymbolAddress(&p, g_H1l); float* H1l = (float*)p;
    cudaGetSymbolAddress(&p, g_Sh);  float* Sh  = (float*)p;
    cudaGetSymbolAddress(&p, g_Sl);  float* Sl  = (float*)p;
    cudaGetSymbolAddress(&p, g_CXh); float* CXh = (float*)p;
    cudaGetSymbolAddress(&p, g_CXl); float* CXl = (float*)p;
    cudaGetSymbolAddress(&p, g_HSh); float* HSh = (float*)p;
    cudaGetSymbolAddress(&p, g_HSl); float* HSl = (float*)p;

    cudaFuncSetAttribute(lstm_seq, cudaFuncAttributeMaxDynamicSharedMemorySize,
                         SMEM_LSTM);
    cudaFuncSetAttribute(gemm_v3, cudaFuncAttributeMaxDynamicSharedMemorySize,
                         SMEM_GEMM);

    // operand splits
    split_tf32<<<TT*BB*EE/1024, 256>>>((const float4*)inputs, (float4*)INh, (float4*)INl);
    split_tf32<<<G4*EE/1024,   256>>>((const float4*)W_ih1, (float4*)W1h, (float4*)W1l);
    split_tf32<<<G4*HH/1024,   256>>>((const float4*)W_ih2, (float4*)W2h, (float4*)W2l);
    split_tf32<<<VV*HH/1024,   256>>>((const float4*)W_out, (float4*)WOh, (float4*)WOl);
    split_tf32<<<UU*BB*HH/1024,256>>>((const float4*)Lst,   (float4*)Lh,  (float4*)Ll);

    // X1 = inputs @ W_ih1^T + biases -> [t][g4][b]
    {
        dim3 g(G4 / 64, (TT * BB) / 128, 1);
        gemm_v3<<<g, 256, SMEM_GEMM>>>(INh, INl, W1h, W1l, X1, 0, 0,
                                       b_ih1, b_hh1,
                                       TT * BB, G4, EE, EE, EE, G4,
                                       0, 0, 0, 1, 0);
    }

    // layer-1 recurrence -> H1 hi/lo
    prep<<<1, 256>>>(h0);
    lstm_seq<<<NBLK, 256, SMEM_LSTM>>>(X1, W_hh1, c0, H1h, H1l);

    // S = H1 @ L^T (batched)
    {
        dim3 g(UU / 64, 1, BB);
        gemm_v3<<<g, 256, SMEM_GEMM>>>(H1h, H1l, Lh, Ll, S, 0, 0,
                                       0, 0,
                                       TT, UU, HH, BB * HH, BB * HH, BB * UU,
                                       HH, HH, UU, 0, 0);
    }
    softmax_split<<<TT * BB, 256>>>(S, Sh, Sl, UU);

    // CTX = softmax(S) @ L (NN), epilogue writes tf32 hi/lo
    {
        dim3 g(HH / 64, 1, BB);
        gemm_v3<<<g, 256, SMEM_GEMM>>>(Sh, Sl, Lh, Ll, 0, CXh, CXl,
                                       0, 0,
                                       TT, HH, UU, BB * UU, BB * HH, BB * HH,
                                       UU, HH, HH, 0, 1);
    }

    // X2 = CTX @ W_ih2^T + biases -> [t][g4][b]
    {
        dim3 g(G4 / 64, (TT * BB) / 128, 1);
        gemm_v3<<<g, 256, SMEM_GEMM>>>(CXh, CXl, W2h, W2l, X2, 0, 0,
                                       b_ih2, b_hh2,
                                       TT * BB, G4, HH, HH, HH, G4,
                                       0, 0, 0, 1, 0);
    }

    // layer-2 recurrence -> HS hi/lo
    prep<<<1, 256>>>(h0 + BB * HH);
    lstm_seq<<<NBLK, 256, SMEM_LSTM>>>(X2, W_hh2, c0 + BB * HH, HSh, HSl);

    // logits = HS @ W_out^T + b_out -> softmax over V
    {
        dim3 g((VV + 63) / 64, (TT * BB) / 128, 1);
        gemm_v3<<<g, 256, SMEM_GEMM>>>(HSh, HSl, WOh, WOl, out, 0, 0,
                                       b_out, 0,
                                       TT * BB, VV, HH, HH, HH, VV,
                                       0, 0, 0, 0, 0);
    }
    softmax_rows<<<TT * BB, 256>>>(out, VV);
}